// round 1
// baseline (speedup 1.0000x reference)
#include <cuda_runtime.h>
#include <math.h>

#define E 4
#define L 10
#define MM 512
#define FF 128
#define SS 1000

// ---------------- device scratch (static: no allocations allowed) ----------
__device__ float    g_proj[E * L * FF * MM];   // proj transposed: [e][l][f][m], 10.5 MB
__device__ float    g_std_partial[E * L];
__device__ float    g_invstd;
__device__ unsigned g_minbits;
__device__ unsigned g_maxbits;

// ordered-uint encoding of float for atomicMin/Max
__device__ __forceinline__ unsigned fenc(float f) {
    unsigned u = __float_as_uint(f);
    return (u & 0x80000000u) ? ~u : (u | 0x80000000u);
}
__device__ __forceinline__ float fdec(unsigned e) {
    unsigned u = (e & 0x80000000u) ? (e ^ 0x80000000u) : ~e;
    return __uint_as_float(u);
}

// ---------------- K0: init global accumulators -----------------------------
__global__ void k0_init() {
    g_minbits = 0xFFFFFFFFu;
    g_maxbits = 0u;
}

// ---------------- K1: per-(e,l) sum of per-feature stds ---------------------
__global__ void k1_std(const float* __restrict__ matrix) {
    int bl = blockIdx.x;          // e*L + l
    int f  = threadIdx.x;         // feature
    const float* base = matrix + (size_t)bl * MM * FF + f;
    float s = 0.f, s2 = 0.f;
#pragma unroll 8
    for (int m = 0; m < MM; m++) {
        float x = base[(size_t)m * FF];
        s += x; s2 += x * x;
    }
    float mean = s * (1.f / MM);
    float var  = fmaxf(s2 * (1.f / MM) - mean * mean, 0.f);
    float sd   = sqrtf(var);
    __shared__ float red[128];
    red[f] = sd; __syncthreads();
    for (int o = 64; o > 0; o >>= 1) { if (f < o) red[f] += red[f + o]; __syncthreads(); }
    if (f == 0) g_std_partial[bl] = red[0];
}

// ---------------- K2: deterministic reduce of std partials ------------------
__global__ void k2_red() {
    int t = threadIdx.x;                       // 64 threads
    float v = (t < E * L) ? g_std_partial[t] : 0.f;
    __shared__ float red[64];
    red[t] = v; __syncthreads();
    for (int o = 32; o > 0; o >>= 1) { if (t < o) red[t] += red[t + o]; __syncthreads(); }
    if (t == 0) {
        float stdv = red[0] / (float)(E * L * FF);
        g_invstd = 1.0f / stdv;
    }
}

// ---------------- K3: proj = (matrix @ params) * invstd, fused min/max ------
// 160 blocks, each computes a 128(m) x 128(g) tile; writes proj transposed.
__global__ __launch_bounds__(256) void k3_gemm(const float* __restrict__ A,
                                               const float* __restrict__ B) {
    __shared__ float As[32 * 129];   // As[k][m]  (A tile transposed)
    __shared__ float Bs[32 * 132];   // Bs[k][g]
    int tid = threadIdx.x;
    int tx = tid & 15, ty = tid >> 4;
    int row0  = blockIdx.x * 128;          // global row = (e*L+l)*M + m
    int el    = row0 / MM;
    int mbase = row0 % MM;

    float acc[8][8];
#pragma unroll
    for (int i = 0; i < 8; i++)
#pragma unroll
        for (int j = 0; j < 8; j++) acc[i][j] = 0.f;

    const float* Ab = A + (size_t)row0 * FF;
    for (int kc = 0; kc < FF; kc += 32) {
#pragma unroll
        for (int t = 0; t < 16; t++) {
            int idx = tid + t * 256;               // 0..4095
            int kk = idx & 31, mm = idx >> 5;      // coalesced global read
            As[kk * 129 + mm] = Ab[(size_t)mm * FF + kc + kk];
        }
#pragma unroll
        for (int t = 0; t < 16; t++) {
            int idx = tid + t * 256;
            int g = idx & 127, kk = idx >> 7;
            Bs[kk * 132 + g] = B[(size_t)(kc + kk) * FF + g];
        }
        __syncthreads();
#pragma unroll
        for (int kk = 0; kk < 32; kk++) {
            float a[8];
#pragma unroll
            for (int i = 0; i < 8; i++) a[i] = As[kk * 129 + ty * 8 + i];
            float4 b0 = *(const float4*)&Bs[kk * 132 + tx * 8];
            float4 b1 = *(const float4*)&Bs[kk * 132 + tx * 8 + 4];
            float b[8] = {b0.x, b0.y, b0.z, b0.w, b1.x, b1.y, b1.z, b1.w};
#pragma unroll
            for (int i = 0; i < 8; i++)
#pragma unroll
                for (int j = 0; j < 8; j++)
                    acc[i][j] = fmaf(a[i], b[j], acc[i][j]);
        }
        __syncthreads();
    }

    float inv = g_invstd;
    float mn = INFINITY, mx = -INFINITY;
#pragma unroll
    for (int j = 0; j < 8; j++) {
        int g = tx * 8 + j;
        float* outp = g_proj + ((size_t)el * FF + g) * MM + mbase + ty * 8;
#pragma unroll
        for (int i = 0; i < 8; i++) {
            float v = acc[i][j] * inv;
            outp[i] = v;
            mn = fminf(mn, v); mx = fmaxf(mx, v);
        }
    }
    __shared__ float rmn[256], rmx[256];
    rmn[tid] = mn; rmx[tid] = mx; __syncthreads();
    for (int o = 128; o > 0; o >>= 1) {
        if (tid < o) {
            rmn[tid] = fminf(rmn[tid], rmn[tid + o]);
            rmx[tid] = fmaxf(rmx[tid], rmx[tid + o]);
        }
        __syncthreads();
    }
    if (tid == 0) {
        atomicMin(&g_minbits, fenc(rmn[0]));
        atomicMax(&g_maxbits, fenc(rmx[0]));
    }
}

// ---------------- K4: KDE grid sums + pairwise L1, fused --------------------
// block = (l,f); 256 threads; thread owns 4 consecutive grid points.
__global__ __launch_bounds__(256) void k4_main(const int* __restrict__ data_len,
                                               const void* __restrict__ itrain,
                                               float* __restrict__ out) {
    int b = blockIdx.x;
    int l = b / FF, f = b % FF;
    int tid = threadIdx.x;

    __shared__ float sv[E][MM];
    __shared__ int   slen[E];
    __shared__ float sinvlen[E];
    for (int e = 0; e < E; e++) {
        const float* src = g_proj + ((size_t)(e * L + l) * FF + f) * MM;
        for (int idx = tid; idx < MM; idx += 256) sv[e][idx] = src[idx];
    }
    if (tid < E) {
        int le = data_len[tid * L + l];
        slen[tid] = le;
        sinvlen[tid] = 1.0f / (float)le;
    }
    __syncthreads();

    float left  = fdec(g_minbits);
    float right = fdec(g_maxbits);
    float step  = (right - left) * (1.0f / (SS - 1));   // linspace spacing
    float delta = (right - left) * (1.0f / SS);         // reference's delta

    // bw = 1.06 * 512^(-1/5) exactly (mean std of normalized matrix == 1)
    const double bwd = 1.06 * exp2(-1.8);
    const double cd  = 0.5 / (bwd * bwd);
    const float qk   = (float)sqrt(cd * 1.4426950408889634); // arg = -(qk*u)^2 in log2
    const float divisor = (float)(2.5066282746310002 * bwd); // sqrt(2*pi)*bw

    int p0 = tid * 4;
    float xs[4];
#pragma unroll
    for (int j = 0; j < 4; j++) xs[j] = left + (float)(p0 + j) * step;
    int warp = tid >> 5;
    float xmid   = left + ((float)(warp * 128) + 63.5f) * step;
    const float W = 2.0f;                      // exp(-c*4) < 5e-10 -> negligible
    float thresh = W + 64.f * step;

    float racc[E][4];
#pragma unroll
    for (int e = 0; e < E; e++)
#pragma unroll
        for (int j = 0; j < 4; j++) racc[e][j] = 0.f;

    for (int e = 0; e < E; e++) {
        int n = slen[e];                        // padded rows are exactly 0 -> skip
        const float* pv = sv[e];
        for (int m = 0; m < n; m++) {
            float v = pv[m];
            if (__any_sync(0xFFFFFFFFu, fabsf(v - xmid) < thresh)) {
#pragma unroll
                for (int j = 0; j < 4; j++) {
                    float u = v - xs[j];
                    float t = u * qk;
                    float arg = -t * t;
                    float g;
                    asm("ex2.approx.ftz.f32 %0, %1;" : "=f"(g) : "f"(arg));
                    racc[e][j] += g;
                }
            }
        }
    }

    // pairwise |r_i - r_j| accumulated over this thread's grid points
    float ps[6];
#pragma unroll
    for (int k = 0; k < 6; k++) ps[k] = 0.f;
#pragma unroll
    for (int j = 0; j < 4; j++) {
        if (p0 + j < SS) {
            float r[E];
#pragma unroll
            for (int e = 0; e < E; e++) r[e] = racc[e][j] * sinvlen[e];
            int k = 0;
#pragma unroll
            for (int i = 0; i < E; i++)
#pragma unroll
                for (int jj = i + 1; jj < E; jj++) {
                    ps[k] += fabsf(r[i] - r[jj]);
                    k++;
                }
        }
    }
    // warp shuffle reduce, then cross-warp via shared
#pragma unroll
    for (int k = 0; k < 6; k++)
#pragma unroll
        for (int o = 16; o > 0; o >>= 1)
            ps[k] += __shfl_down_sync(0xFFFFFFFFu, ps[k], o);
    __shared__ float wred[8][6];
    if ((tid & 31) == 0) {
#pragma unroll
        for (int k = 0; k < 6; k++) wred[warp][k] = ps[k];
    }
    __syncthreads();
    if (tid == 0) {
        float tot[6];
#pragma unroll
        for (int k = 0; k < 6; k++) {
            tot[k] = 0.f;
            for (int w = 0; w < 8; w++) tot[k] += wred[w][k];
        }
        // decode is_train_env robustly (bool bytes vs int32 words)
        const int* wi = (const int*)itrain;
        bool asint = true;
        int vi[E];
        for (int i = 0; i < E; i++) { vi[i] = wi[i]; if (vi[i] != 0 && vi[i] != 1) asint = false; }
        const unsigned char* wb = (const unsigned char*)itrain;
        bool tr[E];
        for (int i = 0; i < E; i++) tr[i] = asint ? (vi[i] != 0) : (wb[i] != 0);

        float scale = delta * 0.5f / divisor;
        float testmax = -INFINITY, trainmax = -INFINITY;
        int k = 0;
        for (int i = 0; i < E; i++)
            for (int jj = i + 1; jj < E; jj++) {
                float h = tot[k] * scale;
                testmax = fmaxf(testmax, h);
                if (tr[i] && tr[jj]) trainmax = fmaxf(trainmax, h);
                k++;
            }
        out[l * FF + f]          = trainmax;             // train_results [L,F]
        out[L * FF + l * FF + f] = testmax;              // test_results  [L,F]
    }
}

// ---------------- K5: final max-over-L, mean-over-F scalars -----------------
__global__ void k5_fin(float* __restrict__ out) {
    int f = threadIdx.x;    // 128
    float mtr = -INFINITY, mte = -INFINITY;
    for (int l = 0; l < L; l++) {
        mtr = fmaxf(mtr, out[l * FF + f]);
        mte = fmaxf(mte, out[L * FF + l * FF + f]);
    }
    __shared__ float r1[128], r2[128];
    r1[f] = mtr; r2[f] = mte; __syncthreads();
    for (int o = 64; o > 0; o >>= 1) {
        if (f < o) { r1[f] += r1[f + o]; r2[f] += r2[f + o]; }
        __syncthreads();
    }
    if (f == 0) {
        out[2 * L * FF]     = r1[0] / (float)FF;   // train_dis
        out[2 * L * FF + 1] = r2[0] / (float)FF;   // test_dis
    }
}

// ---------------- launcher ---------------------------------------------------
extern "C" void kernel_launch(void* const* d_in, const int* in_sizes, int n_in,
                              void* d_out, int out_size) {
    const float* matrix   = (const float*)d_in[0];  // [E,L,M,F]
    const float* params   = (const float*)d_in[1];  // [F,F]
    const int*   data_len = (const int*)d_in[2];    // [E,L]
    const void*  itrain   = d_in[3];                // [E] bool
    float* out = (float*)d_out;                     // 2562 floats

    k0_init<<<1, 1>>>();
    k1_std<<<E * L, 128>>>(matrix);
    k2_red<<<1, 64>>>();
    k3_gemm<<<(E * L * MM) / 128, 256>>>(matrix, params);
    k4_main<<<L * FF, 256>>>(data_len, itrain, out);
    k5_fin<<<1, 128>>>(out);
}